// round 5
// baseline (speedup 1.0000x reference)
#include <cuda_runtime.h>
#include <stdint.h>

#define NEG_FILL -1e20f
#define MAXB 8
#define MAXN 16384

typedef unsigned long long u64;
typedef unsigned int u32;
typedef unsigned short u16;

// scratch (no allocation allowed)
__device__ int g_topidx[MAXB * MAXN];
__device__ u32 g_hi[MAXB * MAXN];
__device__ u16 g_lo[MAXB * MAXN];

__device__ __forceinline__ u32 mono32(float f) {
    u32 u = __float_as_uint(f);
    return (u & 0x80000000u) ? ~u : (u | 0x80000000u);
}
__device__ __forceinline__ float inv_mono32(u32 k) {
    u32 u = (k & 0x80000000u) ? (k ^ 0x80000000u) : ~k;
    return __uint_as_float(u);
}

// prob = max over tags 1..7 of softmax over 8 tags == exp(m1-m)/Z
__device__ __forceinline__ float prob8(const float4* p) {
    float4 a = p[0], b = p[1];
    float m1 = fmaxf(fmaxf(a.y, a.z),
                     fmaxf(a.w, fmaxf(fmaxf(b.x, b.y), fmaxf(b.z, b.w))));
    float m = fmaxf(a.x, m1);
    float z = expf(a.x - m) + expf(a.y - m) + expf(a.z - m) + expf(a.w - m)
            + expf(b.x - m) + expf(b.y - m) + expf(b.z - m) + expf(b.w - m);
    return expf(m1 - m) / z;
}

// ---- Kernel 1: mask-dtype detection (block-local) + prob + split keys ----
__global__ __launch_bounds__(256) void prob_keys(
    const float4* __restrict__ sa4, const float4* __restrict__ sb4,
    const void* __restrict__ mask, int BN, int Nm1)
{
    __shared__ unsigned s_byte;
    const int i0 = blockIdx.x * 256;
    if (threadIdx.x == 0) s_byte = 0;
    __syncthreads();

    const u32* w = (const u32*)mask;
    if (threadIdx.x < 64) {
        u32 v = w[i0 / 4 + threadIdx.x];
        if (v != 0u && v != 1u && v != 0x3F800000u) atomicOr(&s_byte, 1u);
    }
    __syncthreads();
    const unsigned isbyte = s_byte;
    const unsigned char* mb = (const unsigned char*)mask;

    int i = i0 + threadIdx.x;
    if (i >= BN) return;
    float pa = prob8(sa4 + 2 * (size_t)i);
    float pb = prob8(sb4 + 2 * (size_t)i);
    float p = fmaxf(pa, pb);
    bool m = isbyte ? (mb[i] != 0) : (w[i] != 0u);
    float sc = m ? p : NEG_FILL;
    int n = i & Nm1;
    g_hi[i] = mono32(sc);
    g_lo[i] = (u16)(Nm1 - n);  // larger lo == smaller index (tie-break)
}

// ---- block-wide inclusive scan over 1024 threads ----
__device__ __forceinline__ int block_incl_scan(int v, int lane, int warp, int* s_w) {
    int acc = v;
    #pragma unroll
    for (int o = 1; o < 32; o <<= 1) {
        int x = __shfl_up_sync(0xFFFFFFFFu, acc, o);
        if (lane >= o) acc += x;
    }
    if (lane == 31) s_w[warp] = acc;
    __syncthreads();
    if (warp == 0) {
        int x = s_w[lane];
        #pragma unroll
        for (int o = 1; o < 32; o <<= 1) {
            int y = __shfl_up_sync(0xFFFFFFFFu, x, o);
            if (lane >= o) x += y;
        }
        s_w[lane] = x;
    }
    __syncthreads();
    int res = acc + (warp ? s_w[warp - 1] : 0);
    __syncthreads();  // protect s_w for reuse
    return res;
}

// find the bin containing the r-th largest element (descending cumulative);
// writes digit to s_bc[0] and strictly-above count to s_bc[1]
__device__ __forceinline__ void find_digit(const u32* hist, int bins, int r,
                                           int tid, int lane, int warp,
                                           int* s_w, int* s_bc) {
    int ipt = (bins + 1023) >> 10;  // <= 4
    int local[4];
    int lsum = 0;
    int base = bins - 1 - tid * ipt;
    #pragma unroll
    for (int k = 0; k < 4; ++k) {
        int bb = base - k;
        local[k] = (k < ipt && bb >= 0) ? (int)hist[bb] : 0;
        lsum += local[k];
    }
    int incl = block_incl_scan(lsum, lane, warp, s_w);
    int cum = incl - lsum;  // total count in bins above my range
    #pragma unroll
    for (int k = 0; k < 4; ++k) {
        int bb = base - k;
        if (k < ipt && bb >= 0) {
            if (cum < r && cum + local[k] >= r) { s_bc[0] = bb; s_bc[1] = cum; }
            cum += local[k];
        }
    }
    __syncthreads();
}

#define AGG_ATOMIC(ok, bin)                                              \
    do {                                                                 \
        u32 _m = __ballot_sync(0xFFFFFFFFu, (ok));                       \
        if (ok) {                                                        \
            u32 _p = __match_any_sync(_m, (bin));                        \
            if ((int)(__ffs(_p) - 1) == lane)                            \
                atomicAdd(&s_hist[(bin)], __popc(_p));                   \
        }                                                                \
    } while (0)

// radix select on hi32 (12+12+8 bits). map==0 -> identity over [0,n)
__device__ __forceinline__ u32 radix_hi(const u32* hi, const int* map, int n,
                                        int& r, int tid, int lane, int warp,
                                        u32* s_hist, int* s_w, int* s_bc,
                                        int bdim) {
    int nw = (n + bdim - 1) / bdim * bdim;
    u32 pfx;
    // level 0: bits [31:20]
    for (int j = tid; j < 4096; j += bdim) s_hist[j] = 0;
    __syncthreads();
    for (int i = tid; i < nw; i += bdim) {
        bool ok = i < n;
        u32 bin = 0;
        if (ok) { u32 h = map ? hi[map[i]] : hi[i]; bin = h >> 20; }
        AGG_ATOMIC(ok, bin);
    }
    __syncthreads();
    find_digit(s_hist, 4096, r, tid, lane, warp, s_w, s_bc);
    pfx = (u32)s_bc[0];
    r -= s_bc[1];
    __syncthreads();
    // level 1: bits [19:8]
    for (int j = tid; j < 4096; j += bdim) s_hist[j] = 0;
    __syncthreads();
    for (int i = tid; i < nw; i += bdim) {
        bool ok = false;
        u32 bin = 0;
        if (i < n) {
            u32 h = map ? hi[map[i]] : hi[i];
            ok = (h >> 20) == pfx;
            bin = (h >> 8) & 4095u;
        }
        AGG_ATOMIC(ok, bin);
    }
    __syncthreads();
    find_digit(s_hist, 4096, r, tid, lane, warp, s_w, s_bc);
    pfx = (pfx << 12) | (u32)s_bc[0];
    r -= s_bc[1];
    __syncthreads();
    // level 2: bits [7:0]
    for (int j = tid; j < 256; j += bdim) s_hist[j] = 0;
    __syncthreads();
    for (int i = tid; i < nw; i += bdim) {
        bool ok = false;
        u32 bin = 0;
        if (i < n) {
            u32 h = map ? hi[map[i]] : hi[i];
            ok = (h >> 8) == pfx;
            bin = h & 255u;
        }
        AGG_ATOMIC(ok, bin);
    }
    __syncthreads();
    find_digit(s_hist, 256, r, tid, lane, warp, s_w, s_bc);
    pfx = (pfx << 8) | (u32)s_bc[0];
    r -= s_bc[1];
    __syncthreads();
    return pfx;
}

// radix select on lo14 (7+7 bits) over a compact candidate list
__device__ __forceinline__ u32 radix_lo(const u16* cand, int c, int& r,
                                        int tid, int lane, int warp,
                                        u32* s_hist, int* s_w, int* s_bc,
                                        int bdim) {
    int cw = (c + bdim - 1) / bdim * bdim;
    for (int j = tid; j < 128; j += bdim) s_hist[j] = 0;
    __syncthreads();
    for (int i = tid; i < cw; i += bdim) {
        bool ok = i < c;
        u32 bin = ok ? (u32)(cand[i] >> 7) : 0u;
        AGG_ATOMIC(ok, bin);
    }
    __syncthreads();
    find_digit(s_hist, 128, r, tid, lane, warp, s_w, s_bc);
    u32 lp = (u32)s_bc[0];
    r -= s_bc[1];
    __syncthreads();
    for (int j = tid; j < 128; j += bdim) s_hist[j] = 0;
    __syncthreads();
    for (int i = tid; i < cw; i += bdim) {
        bool ok = false;
        u32 bin = 0;
        if (i < c) {
            u32 v = cand[i];
            ok = (v >> 7) == lp;
            bin = v & 127u;
        }
        AGG_ATOMIC(ok, bin);
    }
    __syncthreads();
    find_digit(s_hist, 128, r, tid, lane, warp, s_w, s_bc);
    u32 res = (lp << 7) | (u32)s_bc[0];
    __syncthreads();
    return res;
}

// ---- Kernel 2: per-batch select + ordered compaction + outputs ----
extern __shared__ char s_dyn[];  // [hi N*4][lo N*2][idx K*4][cand N*2]

__global__ __launch_bounds__(1024) void spanprune_select(
    const int* __restrict__ seq_length, float* __restrict__ out,
    int B, int N, int K, int D)
{
    __shared__ u32 s_hist[4096];
    __shared__ int s_w[32];
    __shared__ int s_bc[2];
    __shared__ int s_cnt;

    u32* s_hi = (u32*)s_dyn;
    u16* s_lo = (u16*)(s_dyn + (size_t)N * 4);
    int* s_idx = (int*)(s_dyn + (size_t)N * 6);
    u16* s_cand = (u16*)(s_dyn + (size_t)N * 6 + (size_t)K * 4);

    const int b = blockIdx.x;
    const int tid = threadIdx.x;
    const int bdim = blockDim.x;
    const int lane = tid & 31;
    const int warp = tid >> 5;

    // load split keys (L2-resident)
    const uint4* gh = (const uint4*)(g_hi + (size_t)b * N);
    for (int i = tid; i < N / 4; i += bdim) ((uint4*)s_hi)[i] = gh[i];
    const uint4* gl = (const uint4*)(g_lo + (size_t)b * N);
    for (int i = tid; i < N / 8; i += bdim) ((uint4*)s_lo)[i] = gl[i];
    __syncthreads();

    int sl = seq_length[b];
    int num_keep = sl * 2;
    if (num_keep < 1) num_keep = 1;
    if (num_keep > K) num_keep = K;

    // ---- K-th largest key threshold ----
    int r1 = K;
    u32 hthr1 = radix_hi(s_hi, 0, N, r1, tid, lane, warp, s_hist, s_w, s_bc, bdim);
    if (tid == 0) s_cnt = 0;
    __syncthreads();
    for (int i = tid; i < N; i += bdim)
        if (s_hi[i] == hthr1) { int p = atomicAdd(&s_cnt, 1); s_cand[p] = s_lo[i]; }
    __syncthreads();
    int c1 = s_cnt;
    __syncthreads();
    u32 lthr1 = radix_lo(s_cand, c1, r1, tid, lane, warp, s_hist, s_w, s_bc, bdim);

    // ---- compact top-K in index order (exactly K; keys distinct) ----
    const int CH = N / bdim;
    int base_i = tid * CH;
    int cnt = 0;
    #pragma unroll 4
    for (int k2 = 0; k2 < CH; ++k2) {
        u32 h = s_hi[base_i + k2];
        u32 lo = s_lo[base_i + k2];
        if (h > hthr1 || (h == hthr1 && lo >= lthr1)) cnt++;
    }
    int incl = block_incl_scan(cnt, lane, warp, s_w);
    int pos = incl - cnt;
    for (int k2 = 0; k2 < CH; ++k2) {
        int i = base_i + k2;
        u32 h = s_hi[i];
        u32 lo = s_lo[i];
        if (h > hthr1 || (h == hthr1 && lo >= lthr1)) s_idx[pos++] = i;
    }
    __syncthreads();

    // ---- num_keep-th threshold among the K list ----
    u32 hthr0 = hthr1, lthr0 = lthr1;
    if (num_keep < K) {
        int r0 = num_keep;
        hthr0 = radix_hi(s_hi, s_idx, K, r0, tid, lane, warp, s_hist, s_w, s_bc, bdim);
        if (tid == 0) s_cnt = 0;
        __syncthreads();
        int Kw = (K + bdim - 1) / bdim * bdim;
        for (int p = tid; p < Kw; p += bdim) {
            if (p < K && s_hi[s_idx[p]] == hthr0) {
                int q = atomicAdd(&s_cnt, 1);
                s_cand[q] = s_lo[s_idx[p]];
            }
        }
        __syncthreads();
        int c0 = s_cnt;
        __syncthreads();
        lthr0 = radix_lo(s_cand, c0, r0, tid, lane, warp, s_hist, s_w, s_bc, bdim);
    }

    // ---- outputs ----
    int fill = s_idx[K - 1];  // max index among top-K (list is index-sorted)
    const u32 negk = mono32(NEG_FILL);
    float* idx_out = out;
    float* sc_out = out + (size_t)B * K * (1 + D);
    float* mk_out = sc_out + (size_t)B * K;
    int* gt = g_topidx + (size_t)b * N;
    const size_t obase = (size_t)b * K;

    int CH2 = (K + bdim - 1) / bdim;
    int b2 = tid * CH2;
    int cnt2 = 0;
    for (int k2 = 0; k2 < CH2; ++k2) {
        int p = b2 + k2;
        if (p < K) {
            u32 h = s_hi[s_idx[p]];
            u32 lo = s_lo[s_idx[p]];
            if (h > hthr0 || (h == hthr0 && lo >= lthr0)) cnt2++;
        }
    }
    int incl2 = block_incl_scan(cnt2, lane, warp, s_w);
    int q = incl2 - cnt2;
    for (int k2 = 0; k2 < CH2; ++k2) {
        int p = b2 + k2;
        if (p < K) {
            int idx = s_idx[p];
            u32 h = s_hi[idx];
            u32 lo = s_lo[idx];
            if (h > hthr0 || (h == hthr0 && lo >= lthr0)) {
                int j = q++;
                gt[j] = idx;
                idx_out[obase + j] = (float)idx;
                sc_out[obase + j] = inv_mono32(h);
                mk_out[obase + j] = (h != negk) ? 1.0f : 0.0f;
            }
        }
    }
    // padding entries j in [num_keep, K)
    u32 kmf = s_hi[fill];
    float scf = inv_mono32(kmf);
    for (int j = num_keep + tid; j < K; j += bdim) {
        gt[j] = fill;
        idx_out[obase + j] = (float)fill;
        sc_out[obase + j] = scf;
        mk_out[obase + j] = 0.0f;
    }
}

// ---- Kernel 3: embedding gather — one warp per row, streaming loads ----
__global__ __launch_bounds__(256) void spanprune_gather(
    const float* __restrict__ emb, float* __restrict__ out_emb,
    int N, int D, int K, int total_threads)
{
    int t = blockIdx.x * blockDim.x + threadIdx.x;
    if (t >= total_threads) return;
    int lane = t & 31;
    int row = t >> 5;
    int b = row / K;
    int j = row - b * K;
    int idx = g_topidx[b * N + j];
    const float4* src = (const float4*)(emb + ((size_t)b * N + idx) * D);
    float4* dst = (float4*)(out_emb + (size_t)row * D);
    int nv = D >> 2;
    #pragma unroll 2
    for (int c = lane; c < nv; c += 32)
        dst[c] = __ldcs(&src[c]);
}

extern "C" void kernel_launch(void* const* d_in, const int* in_sizes, int n_in,
                              void* d_out, int out_size)
{
    const float* emb = (const float*)d_in[0];
    const float4* sa = (const float4*)d_in[1];
    const float4* sb = (const float4*)d_in[2];
    const void* sm = d_in[3];
    const int* sl = (const int*)d_in[4];

    int B = in_sizes[4];                 // 8
    int BN = in_sizes[3];                // B*N
    int N = BN / B;                      // 16384
    int D = in_sizes[0] / BN;            // 256
    int K = out_size / (B * (D + 3));    // max_keep

    prob_keys<<<(BN + 255) / 256, 256>>>(sa, sb, sm, BN, N - 1);

    size_t smem = (size_t)N * 8 + (size_t)K * 4;  // hi+lo+cand + idx
    cudaFuncSetAttribute(spanprune_select,
                         cudaFuncAttributeMaxDynamicSharedMemorySize,
                         (int)smem);
    spanprune_select<<<B, 1024, smem>>>(sl, (float*)d_out, B, N, K, D);

    int total_threads = B * K * 32;  // one warp per output row
    int threads = 256;
    int blocks = (total_threads + threads - 1) / threads;
    spanprune_gather<<<blocks, threads>>>(emb, (float*)d_out + (size_t)B * K,
                                          N, D, K, total_threads);
}

// round 6
// speedup vs baseline: 1.3033x; 1.3033x over previous
#include <cuda_runtime.h>
#include <stdint.h>

#define NEG_FILL -1e20f
#define MAXB 8
#define MAXN 16384

typedef unsigned long long u64;
typedef unsigned int u32;
typedef unsigned short u16;

// scratch (no allocation allowed)
__device__ int g_topidx[MAXB * MAXN];
__device__ u32 g_hi[MAXB * MAXN];
__device__ u16 g_lo[MAXB * MAXN];

__device__ __forceinline__ u32 mono32(float f) {
    u32 u = __float_as_uint(f);
    return (u & 0x80000000u) ? ~u : (u | 0x80000000u);
}
__device__ __forceinline__ float inv_mono32(u32 k) {
    u32 u = (k & 0x80000000u) ? (k ^ 0x80000000u) : ~k;
    return __uint_as_float(u);
}

// prob = max over tags 1..7 of softmax over 8 tags == exp(m1-m)/Z
__device__ __forceinline__ float prob8(const float4* p) {
    float4 a = p[0], b = p[1];
    float m1 = fmaxf(fmaxf(a.y, a.z),
                     fmaxf(a.w, fmaxf(fmaxf(b.x, b.y), fmaxf(b.z, b.w))));
    float m = fmaxf(a.x, m1);
    float z = expf(a.x - m) + expf(a.y - m) + expf(a.z - m) + expf(a.w - m)
            + expf(b.x - m) + expf(b.y - m) + expf(b.z - m) + expf(b.w - m);
    return expf(m1 - m) / z;
}

// ---- Kernel 1: mask-dtype detection (block-local) + prob + split keys ----
__global__ __launch_bounds__(256) void prob_keys(
    const float4* __restrict__ sa4, const float4* __restrict__ sb4,
    const void* __restrict__ mask, int BN, int Nm1)
{
    __shared__ unsigned s_byte;
    const int i0 = blockIdx.x * 256;
    if (threadIdx.x == 0) s_byte = 0;
    __syncthreads();

    const u32* w = (const u32*)mask;
    if (threadIdx.x < 64) {
        u32 v = w[i0 / 4 + threadIdx.x];
        if (v != 0u && v != 1u && v != 0x3F800000u) atomicOr(&s_byte, 1u);
    }
    __syncthreads();
    const unsigned isbyte = s_byte;
    const unsigned char* mb = (const unsigned char*)mask;

    int i = i0 + threadIdx.x;
    if (i >= BN) return;
    float pa = prob8(sa4 + 2 * (size_t)i);
    float pb = prob8(sb4 + 2 * (size_t)i);
    float p = fmaxf(pa, pb);
    bool m = isbyte ? (mb[i] != 0) : (w[i] != 0u);
    float sc = m ? p : NEG_FILL;
    int n = i & Nm1;
    g_hi[i] = mono32(sc);
    g_lo[i] = (u16)(Nm1 - n);  // larger lo == smaller index (tie-break)
}

// ---- select kernel shared state ----
__device__ __forceinline__ int block_scan_incl(int v, int lane, int warp,
                                               int* s_w) {
    int acc = v;
    #pragma unroll
    for (int o = 1; o < 32; o <<= 1) {
        int x = __shfl_up_sync(0xFFFFFFFFu, acc, o);
        if (lane >= o) acc += x;
    }
    if (lane == 31) s_w[warp] = acc;
    __syncthreads();
    if (warp == 0) {
        int x = s_w[lane];
        #pragma unroll
        for (int o = 1; o < 32; o <<= 1) {
            int y = __shfl_up_sync(0xFFFFFFFFu, x, o);
            if (lane >= o) x += y;
        }
        s_w[lane] = x;
    }
    __syncthreads();
    int res = acc + (warp ? s_w[warp - 1] : 0);
    __syncthreads();
    return res;
}

// find bin containing r-th largest (descending); s_bc[off]=digit, s_bc[off+1]=above
__device__ __forceinline__ void find_digit(const u32* hist, int bins, int r,
                                           int tid, int lane, int warp,
                                           int* s_w, int* s_bc, int off) {
    int ipt = (bins + 1023) >> 10;  // <= 4
    int local[4];
    int lsum = 0;
    int base = bins - 1 - tid * ipt;
    #pragma unroll
    for (int k = 0; k < 4; ++k) {
        int bb = base - k;
        local[k] = (k < ipt && bb >= 0) ? (int)hist[bb] : 0;
        lsum += local[k];
    }
    int incl = block_scan_incl(lsum, lane, warp, s_w);
    int cum = incl - lsum;
    #pragma unroll
    for (int k = 0; k < 4; ++k) {
        int bb = base - k;
        if (k < ipt && bb >= 0) {
            if (cum < r && cum + local[k] >= r) { s_bc[off] = bb; s_bc[off + 1] = cum; }
            cum += local[k];
        }
    }
    __syncthreads();
}

// 7+7-bit radix select over a compact u16 candidate list (values distinct)
__device__ __forceinline__ u32 radix_lo(const u16* cand, int c, int r,
                                        int tid, int lane, int warp, int bdim,
                                        u32* s_hist, int* s_w, int* s_bc) {
    for (int j = tid; j < 128; j += bdim) s_hist[j] = 0;
    __syncthreads();
    for (int i = tid; i < c; i += bdim) atomicAdd(&s_hist[cand[i] >> 7], 1u);
    __syncthreads();
    find_digit(s_hist, 128, r, tid, lane, warp, s_w, s_bc, 0);
    u32 lp = (u32)s_bc[0];
    r -= s_bc[1];
    __syncthreads();
    for (int j = tid; j < 128; j += bdim) s_hist[j] = 0;
    __syncthreads();
    for (int i = tid; i < c; i += bdim) {
        u32 v = cand[i];
        if ((v >> 7) == lp) atomicAdd(&s_hist[v & 127u], 1u);
    }
    __syncthreads();
    find_digit(s_hist, 128, r, tid, lane, warp, s_w, s_bc, 0);
    u32 res = (lp << 7) | (u32)s_bc[0];
    __syncthreads();
    return res;
}

// dynamic smem: [hi N*4][lo N*2][cand0 N*2][cand1 N*2] = N*10 bytes
extern __shared__ char s_dyn[];

__global__ __launch_bounds__(1024) void spanprune_select(
    const int* __restrict__ seq_length, float* __restrict__ out,
    int B, int N, int K, int D)
{
    __shared__ u32 s_hist0[4096];
    __shared__ u32 s_hist1[4096];
    __shared__ int s_w[32];
    __shared__ int s_bc[4];
    __shared__ int s_cnt[2];
    __shared__ int s_fill;

    u32* s_hi = (u32*)s_dyn;
    u16* s_lo = (u16*)(s_dyn + (size_t)N * 4);
    u16* s_cand0 = (u16*)(s_dyn + (size_t)N * 6);
    u16* s_cand1 = (u16*)(s_dyn + (size_t)N * 8);

    const int b = blockIdx.x;
    const int tid = threadIdx.x;
    const int bdim = blockDim.x;
    const int lane = tid & 31;
    const int warp = tid >> 5;

    int sl = seq_length[b];
    int num_keep = sl * 2;
    if (num_keep < 1) num_keep = 1;
    if (num_keep > K) num_keep = K;

    // ---- level 0 (bits [31:20]) fused with key load; shared histogram ----
    for (int j = tid; j < 4096; j += bdim) s_hist0[j] = 0;
    if (tid == 0) s_fill = 0;
    __syncthreads();

    const u32* gh = g_hi + (size_t)b * N;
    const int nw = (N + bdim - 1) / bdim * bdim;
    for (int i = tid; i < nw; i += bdim) {
        bool ok = i < N;
        u32 bin = 0;
        if (ok) {
            u32 h = __ldg(&gh[i]);
            s_hi[i] = h;
            bin = h >> 20;
        }
        u32 msk = __ballot_sync(0xFFFFFFFFu, ok);
        if (ok) {
            u32 peers = __match_any_sync(msk, bin);
            if ((int)(__ffs(peers) - 1) == lane)
                atomicAdd(&s_hist0[bin], __popc(peers));
        }
    }
    // lo load (word-copied)
    {
        const u32* gl = (const u32*)(g_lo + (size_t)b * N);
        u32* sl32 = (u32*)s_lo;
        for (int i = tid; i < N / 2; i += bdim) sl32[i] = gl[i];
    }
    __syncthreads();

    int r0 = num_keep, r1 = K;
    find_digit(s_hist0, 4096, r0, tid, lane, warp, s_w, s_bc, 0);
    find_digit(s_hist0, 4096, r1, tid, lane, warp, s_w, s_bc, 2);
    u32 pfx0 = (u32)s_bc[0]; r0 -= s_bc[1];
    u32 pfx1 = (u32)s_bc[2]; r1 -= s_bc[3];
    bool same = (pfx0 == pfx1);
    __syncthreads();

    // ---- level 1 (bits [19:8]) ----
    for (int j = tid; j < 4096; j += bdim) { s_hist0[j] = 0; s_hist1[j] = 0; }
    __syncthreads();
    for (int i = tid; i < N; i += bdim) {
        u32 h = s_hi[i];
        u32 top = h >> 20;
        if (top == pfx0) atomicAdd(&s_hist0[(h >> 8) & 4095u], 1u);
        if (!same && top == pfx1) atomicAdd(&s_hist1[(h >> 8) & 4095u], 1u);
    }
    __syncthreads();
    find_digit(s_hist0, 4096, r0, tid, lane, warp, s_w, s_bc, 0);
    find_digit(same ? s_hist0 : s_hist1, 4096, r1, tid, lane, warp, s_w, s_bc, 2);
    pfx0 = (pfx0 << 12) | (u32)s_bc[0]; r0 -= s_bc[1];
    pfx1 = (pfx1 << 12) | (u32)s_bc[2]; r1 -= s_bc[3];
    same = (pfx0 == pfx1);
    __syncthreads();

    // ---- level 2 (bits [7:0]) ----
    for (int j = tid; j < 256; j += bdim) { s_hist0[j] = 0; s_hist1[j] = 0; }
    __syncthreads();
    for (int i = tid; i < N; i += bdim) {
        u32 h = s_hi[i];
        u32 top = h >> 8;
        if (top == pfx0) atomicAdd(&s_hist0[h & 255u], 1u);
        if (!same && top == pfx1) atomicAdd(&s_hist1[h & 255u], 1u);
    }
    __syncthreads();
    find_digit(s_hist0, 256, r0, tid, lane, warp, s_w, s_bc, 0);
    find_digit(same ? s_hist0 : s_hist1, 256, r1, tid, lane, warp, s_w, s_bc, 2);
    u32 hthr0 = (pfx0 << 8) | (u32)s_bc[0]; r0 -= s_bc[1];
    u32 hthr1 = (pfx1 << 8) | (u32)s_bc[2]; r1 -= s_bc[3];
    same = (hthr0 == hthr1);
    if (tid < 2) s_cnt[tid] = 0;
    __syncthreads();

    // ---- candidate gather for lo tie-break ----
    for (int i = tid; i < N; i += bdim) {
        u32 h = s_hi[i];
        if (h == hthr0) { int p = atomicAdd(&s_cnt[0], 1); s_cand0[p] = s_lo[i]; }
        if (!same && h == hthr1) { int p = atomicAdd(&s_cnt[1], 1); s_cand1[p] = s_lo[i]; }
    }
    __syncthreads();
    int c0 = s_cnt[0];
    int c1 = same ? c0 : s_cnt[1];
    const u16* candB = same ? s_cand0 : s_cand1;
    __syncthreads();
    u32 lthr0 = radix_lo(s_cand0, c0, r0, tid, lane, warp, bdim, s_hist0, s_w, s_bc);
    u32 lthr1 = radix_lo(candB, c1, r1, tid, lane, warp, bdim, s_hist0, s_w, s_bc);

    // ---- conflict-free ordered compaction (pass A: ballots + counts) ----
    const int ntiles = (N + bdim - 1) / bdim;
    for (int tile = 0; tile < ntiles; ++tile) {
        int i = tile * bdim + tid;
        bool p0 = false, p1 = false;
        if (i < N) {
            u32 h = s_hi[i];
            u32 lo = s_lo[i];
            p0 = (h > hthr0) || (h == hthr0 && lo >= lthr0);
            p1 = (h > hthr1) || (h == hthr1 && lo >= lthr1);
        }
        u32 b0 = __ballot_sync(0xFFFFFFFFu, p0);
        u32 b1 = __ballot_sync(0xFFFFFFFFu, p1);
        if (lane == 0) {
            s_hist0[tile * 32 + warp] = b0;
            s_hist1[tile * 32 + warp] = (u32)__popc(b0);
            if (b1) atomicMax(&s_fill, tile * bdim + warp * 32 + (31 - __clz(b1)));
        }
    }
    __syncthreads();
    // exclusive scan of per-(tile,warp) counts
    {
        int nitems = ntiles * 32;  // <= 1024 for N <= 32768
        int v = (tid < nitems) ? (int)s_hist1[tid] : 0;
        int incl = block_scan_incl(v, lane, warp, s_w);
        if (tid < nitems) s_hist1[tid] = (u32)(incl - v);
        __syncthreads();
    }

    // ---- pass B: write outputs (no syncs) ----
    const u32 negk = mono32(NEG_FILL);
    float* idx_out = out;
    float* sc_out = out + (size_t)B * K * (1 + D);
    float* mk_out = sc_out + (size_t)B * K;
    int* gt = g_topidx + (size_t)b * N;
    const size_t obase = (size_t)b * K;

    for (int tile = 0; tile < ntiles; ++tile) {
        int i = tile * bdim + tid;
        if (i >= N) break;
        u32 bal = s_hist0[tile * 32 + warp];
        if ((bal >> lane) & 1u) {
            int j = (int)s_hist1[tile * 32 + warp]
                  + __popc(bal & ((1u << lane) - 1u));
            u32 h = s_hi[i];
            gt[j] = i;
            idx_out[obase + j] = (float)i;
            sc_out[obase + j] = inv_mono32(h);
            mk_out[obase + j] = (h != negk) ? 1.0f : 0.0f;
        }
    }

    // padding j in [num_keep, K): fill = max index among top-K
    int fill = s_fill;
    u32 kmf = s_hi[fill];
    float scf = inv_mono32(kmf);
    for (int j = num_keep + tid; j < K; j += bdim) {
        gt[j] = fill;
        idx_out[obase + j] = (float)fill;
        sc_out[obase + j] = scf;
        mk_out[obase + j] = 0.0f;
    }
}

// ---- Kernel 3: embedding gather (R3 known-good form) ----
__global__ __launch_bounds__(256) void spanprune_gather(
    const float* __restrict__ emb, float* __restrict__ out_emb,
    int N, int D, int K, int total_vec)
{
    int t = blockIdx.x * blockDim.x + threadIdx.x;
    if (t >= total_vec) return;
    int per_row = D >> 2;
    int row = t / per_row;
    int c = t - row * per_row;
    int b = row / K;
    int j = row - b * K;
    int idx = g_topidx[b * N + j];
    float4 v = ((const float4*)(emb + ((size_t)b * N + idx) * D))[c];
    ((float4*)(out_emb + (size_t)row * D))[c] = v;
}

extern "C" void kernel_launch(void* const* d_in, const int* in_sizes, int n_in,
                              void* d_out, int out_size)
{
    const float* emb = (const float*)d_in[0];
    const float4* sa = (const float4*)d_in[1];
    const float4* sb = (const float4*)d_in[2];
    const void* sm = d_in[3];
    const int* sl = (const int*)d_in[4];

    int B = in_sizes[4];                 // 8
    int BN = in_sizes[3];                // B*N
    int N = BN / B;                      // 16384
    int D = in_sizes[0] / BN;            // 256
    int K = out_size / (B * (D + 3));    // max_keep

    prob_keys<<<(BN + 255) / 256, 256>>>(sa, sb, sm, BN, N - 1);

    size_t smem = (size_t)N * 10;  // hi + lo + 2 cand lists = 160 KB
    cudaFuncSetAttribute(spanprune_select,
                         cudaFuncAttributeMaxDynamicSharedMemorySize,
                         (int)smem);
    spanprune_select<<<B, 1024, smem>>>(sl, (float*)d_out, B, N, K, D);

    int total_vec = B * K * (D / 4);
    int threads = 256;
    int blocks = (total_vec + threads - 1) / threads;
    spanprune_gather<<<blocks, threads>>>(emb, (float*)d_out + (size_t)B * K,
                                          N, D, K, total_vec);
}

// round 7
// speedup vs baseline: 1.3723x; 1.0530x over previous
#include <cuda_runtime.h>
#include <stdint.h>

#define NEG_FILL -1e20f
#define MAXB 8
#define MAXN 16384

typedef unsigned long long u64;
typedef unsigned int u32;
typedef unsigned short u16;

// scratch (no allocation allowed)
__device__ int g_topidx[MAXB * MAXN];
__device__ u32 g_hi[MAXB * MAXN];
__device__ u16 g_lo[MAXB * MAXN];

__device__ __forceinline__ u32 mono32(float f) {
    u32 u = __float_as_uint(f);
    return (u & 0x80000000u) ? ~u : (u | 0x80000000u);
}
__device__ __forceinline__ float inv_mono32(u32 k) {
    u32 u = (k & 0x80000000u) ? (k ^ 0x80000000u) : ~k;
    return __uint_as_float(u);
}

// prob = max over tags 1..7 of softmax over 8 tags == exp(m1-m)/Z
__device__ __forceinline__ float prob8(const float4* p) {
    float4 a = p[0], b = p[1];
    float m1 = fmaxf(fmaxf(a.y, a.z),
                     fmaxf(a.w, fmaxf(fmaxf(b.x, b.y), fmaxf(b.z, b.w))));
    float m = fmaxf(a.x, m1);
    float z = expf(a.x - m) + expf(a.y - m) + expf(a.z - m) + expf(a.w - m)
            + expf(b.x - m) + expf(b.y - m) + expf(b.z - m) + expf(b.w - m);
    return expf(m1 - m) / z;
}

// ---- Kernel 1: mask detection + prob + split keys (2 elems/thread, MLP) ----
__global__ __launch_bounds__(256) void prob_keys(
    const float4* __restrict__ sa4, const float4* __restrict__ sb4,
    const void* __restrict__ mask, int BN, int Nm1)
{
    __shared__ unsigned s_byte;
    const int i0 = blockIdx.x * 512;
    if (threadIdx.x == 0) s_byte = 0;
    __syncthreads();

    const u32* w = (const u32*)mask;
    if (threadIdx.x < 128) {
        u32 v = w[i0 / 4 + threadIdx.x];
        if (v != 0u && v != 1u && v != 0x3F800000u) atomicOr(&s_byte, 1u);
    }
    __syncthreads();
    const unsigned isbyte = s_byte;
    const unsigned char* mb = (const unsigned char*)mask;

    int i1 = i0 + threadIdx.x;
    int i2 = i1 + 256;
    // independent load chains for both elements -> doubled MLP
    float p1 = 0.f, p2 = 0.f;
    if (i1 < BN)
        p1 = fmaxf(prob8(sa4 + 2 * (size_t)i1), prob8(sb4 + 2 * (size_t)i1));
    if (i2 < BN)
        p2 = fmaxf(prob8(sa4 + 2 * (size_t)i2), prob8(sb4 + 2 * (size_t)i2));
    if (i1 < BN) {
        bool m = isbyte ? (mb[i1] != 0) : (w[i1] != 0u);
        g_hi[i1] = mono32(m ? p1 : NEG_FILL);
        g_lo[i1] = (u16)(Nm1 - (i1 & Nm1));
    }
    if (i2 < BN) {
        bool m = isbyte ? (mb[i2] != 0) : (w[i2] != 0u);
        g_hi[i2] = mono32(m ? p2 : NEG_FILL);
        g_lo[i2] = (u16)(Nm1 - (i2 & Nm1));
    }
}

// ---- block-wide inclusive scan ----
__device__ __forceinline__ int block_scan_incl(int v, int lane, int warp,
                                               int* s_w) {
    int acc = v;
    #pragma unroll
    for (int o = 1; o < 32; o <<= 1) {
        int x = __shfl_up_sync(0xFFFFFFFFu, acc, o);
        if (lane >= o) acc += x;
    }
    if (lane == 31) s_w[warp] = acc;
    __syncthreads();
    if (warp == 0) {
        int x = s_w[lane];
        #pragma unroll
        for (int o = 1; o < 32; o <<= 1) {
            int y = __shfl_up_sync(0xFFFFFFFFu, x, o);
            if (lane >= o) x += y;
        }
        s_w[lane] = x;
    }
    __syncthreads();
    int res = acc + (warp ? s_w[warp - 1] : 0);
    __syncthreads();
    return res;
}

// dual crossing search in ONE packed block scan.
// hA with rank rA -> s_bc[0]=digit, s_bc[1]=above; hB/rB -> s_bc[2],s_bc[3].
// counts per hist <= 16384 so (a<<16)|b accumulates without cross-carry.
__device__ __forceinline__ void find_digit2(const u32* hA, const u32* hB,
                                            int bins, int rA, int rB,
                                            int tid, int lane, int warp,
                                            int* s_w, int* s_bc) {
    int ipt = (bins + 1023) >> 10;  // <= 4
    u32 la[4], lb[4];
    u32 lsum = 0;
    int base = bins - 1 - tid * ipt;
    #pragma unroll
    for (int k = 0; k < 4; ++k) {
        int bb = base - k;
        bool v = (k < ipt && bb >= 0);
        la[k] = v ? hA[bb] : 0u;
        lb[k] = v ? hB[bb] : 0u;
        lsum += (la[k] << 16) | lb[k];
    }
    u32 incl = (u32)block_scan_incl((int)lsum, lane, warp, s_w);
    u32 cum = incl - lsum;
    int cumA = (int)(cum >> 16), cumB = (int)(cum & 0xFFFFu);
    #pragma unroll
    for (int k = 0; k < 4; ++k) {
        int bb = base - k;
        if (k < ipt && bb >= 0) {
            if (cumA < rA && cumA + (int)la[k] >= rA) { s_bc[0] = bb; s_bc[1] = cumA; }
            cumA += (int)la[k];
            if (cumB < rB && cumB + (int)lb[k] >= rB) { s_bc[2] = bb; s_bc[3] = cumB; }
            cumB += (int)lb[k];
        }
    }
    __syncthreads();
}

// dynamic smem: [hi N*4][lo N*2][cand0 N*2][cand1 N*2] = N*10 bytes
extern __shared__ char s_dyn[];

__global__ __launch_bounds__(1024) void spanprune_select(
    const int* __restrict__ seq_length, float* __restrict__ out,
    int B, int N, int K, int D)
{
    __shared__ u32 s_hist0[4096];
    __shared__ u32 s_hist1[4096];
    __shared__ int s_w[32];
    __shared__ int s_bc[4];
    __shared__ int s_cnt[2];
    __shared__ int s_fill;

    u32* s_hi = (u32*)s_dyn;
    u16* s_lo = (u16*)(s_dyn + (size_t)N * 4);
    u16* s_cand0 = (u16*)(s_dyn + (size_t)N * 6);
    u16* s_cand1 = (u16*)(s_dyn + (size_t)N * 8);

    const int b = blockIdx.x;
    const int tid = threadIdx.x;
    const int bdim = blockDim.x;
    const int lane = tid & 31;
    const int warp = tid >> 5;

    int sl = seq_length[b];
    int num_keep = sl * 2;
    if (num_keep < 1) num_keep = 1;
    if (num_keep > K) num_keep = K;

    // ---- level 0 (bits [31:20]) fused with key load ----
    for (int j = tid; j < 4096; j += bdim) s_hist0[j] = 0;
    if (tid == 0) s_fill = 0;
    __syncthreads();

    const u32* gh = g_hi + (size_t)b * N;
    const int nw = (N + bdim - 1) / bdim * bdim;
    for (int i = tid; i < nw; i += bdim) {
        bool ok = i < N;
        u32 bin = 0;
        if (ok) {
            u32 h = __ldg(&gh[i]);
            s_hi[i] = h;
            bin = h >> 20;
        }
        u32 msk = __ballot_sync(0xFFFFFFFFu, ok);
        if (ok) {
            u32 peers = __match_any_sync(msk, bin);
            if ((int)(__ffs(peers) - 1) == lane)
                atomicAdd(&s_hist0[bin], __popc(peers));
        }
    }
    {
        const u32* gl = (const u32*)(g_lo + (size_t)b * N);
        u32* sl32 = (u32*)s_lo;
        for (int i = tid; i < N / 2; i += bdim) sl32[i] = gl[i];
    }
    __syncthreads();

    int r0 = num_keep, r1 = K;
    find_digit2(s_hist0, s_hist0, 4096, r0, r1, tid, lane, warp, s_w, s_bc);
    u32 pfx0 = (u32)s_bc[0]; r0 -= s_bc[1];
    u32 pfx1 = (u32)s_bc[2]; r1 -= s_bc[3];
    bool same = (pfx0 == pfx1);
    __syncthreads();

    // ---- level 1 (bits [19:8]) ----
    for (int j = tid; j < 4096; j += bdim) { s_hist0[j] = 0; s_hist1[j] = 0; }
    __syncthreads();
    for (int i = tid; i < N; i += bdim) {
        u32 h = s_hi[i];
        u32 top = h >> 20;
        if (top == pfx0) atomicAdd(&s_hist0[(h >> 8) & 4095u], 1u);
        if (!same && top == pfx1) atomicAdd(&s_hist1[(h >> 8) & 4095u], 1u);
    }
    __syncthreads();
    find_digit2(s_hist0, same ? s_hist0 : s_hist1, 4096, r0, r1,
                tid, lane, warp, s_w, s_bc);
    pfx0 = (pfx0 << 12) | (u32)s_bc[0]; r0 -= s_bc[1];
    pfx1 = (pfx1 << 12) | (u32)s_bc[2]; r1 -= s_bc[3];
    same = (pfx0 == pfx1);
    __syncthreads();

    // ---- level 2 (bits [7:0]) ----
    for (int j = tid; j < 256; j += bdim) { s_hist0[j] = 0; s_hist1[j] = 0; }
    __syncthreads();
    for (int i = tid; i < N; i += bdim) {
        u32 h = s_hi[i];
        u32 top = h >> 8;
        if (top == pfx0) atomicAdd(&s_hist0[h & 255u], 1u);
        if (!same && top == pfx1) atomicAdd(&s_hist1[h & 255u], 1u);
    }
    __syncthreads();
    find_digit2(s_hist0, same ? s_hist0 : s_hist1, 256, r0, r1,
                tid, lane, warp, s_w, s_bc);
    u32 hthr0 = (pfx0 << 8) | (u32)s_bc[0]; r0 -= s_bc[1];
    u32 hthr1 = (pfx1 << 8) | (u32)s_bc[2]; r1 -= s_bc[3];
    same = (hthr0 == hthr1);
    if (tid < 2) s_cnt[tid] = 0;
    __syncthreads();

    // ---- candidate gather for lo tie-break ----
    for (int i = tid; i < N; i += bdim) {
        u32 h = s_hi[i];
        if (h == hthr0) { int p = atomicAdd(&s_cnt[0], 1); s_cand0[p] = s_lo[i]; }
        if (!same && h == hthr1) { int p = atomicAdd(&s_cnt[1], 1); s_cand1[p] = s_lo[i]; }
    }
    __syncthreads();
    int c0 = s_cnt[0];
    int c1 = same ? c0 : s_cnt[1];
    const u16* candB = same ? s_cand0 : s_cand1;
    __syncthreads();

    // ---- lo14 radix (7+7), both thresholds in halves of one 256-bin array ----
    for (int j = tid; j < 256; j += bdim) s_hist0[j] = 0;
    __syncthreads();
    for (int i = tid; i < c0; i += bdim) atomicAdd(&s_hist0[s_cand0[i] >> 7], 1u);
    for (int i = tid; i < c1; i += bdim) atomicAdd(&s_hist0[128 + (candB[i] >> 7)], 1u);
    __syncthreads();
    find_digit2(s_hist0, s_hist0 + 128, 128, r0, r1, tid, lane, warp, s_w, s_bc);
    u32 lp0 = (u32)s_bc[0]; r0 -= s_bc[1];
    u32 lp1 = (u32)s_bc[2]; r1 -= s_bc[3];
    __syncthreads();
    for (int j = tid; j < 256; j += bdim) s_hist0[j] = 0;
    __syncthreads();
    for (int i = tid; i < c0; i += bdim) {
        u32 v = s_cand0[i];
        if ((v >> 7) == lp0) atomicAdd(&s_hist0[v & 127u], 1u);
    }
    for (int i = tid; i < c1; i += bdim) {
        u32 v = candB[i];
        if ((v >> 7) == lp1) atomicAdd(&s_hist0[128 + (v & 127u)], 1u);
    }
    __syncthreads();
    find_digit2(s_hist0, s_hist0 + 128, 128, r0, r1, tid, lane, warp, s_w, s_bc);
    u32 lthr0 = (lp0 << 7) | (u32)s_bc[0];
    u32 lthr1 = (lp1 << 7) | (u32)s_bc[2];
    __syncthreads();

    // ---- conflict-free ordered compaction (pass A: ballots + counts) ----
    const int ntiles = (N + bdim - 1) / bdim;
    for (int tile = 0; tile < ntiles; ++tile) {
        int i = tile * bdim + tid;
        bool p0 = false, p1 = false;
        if (i < N) {
            u32 h = s_hi[i];
            u32 lo = s_lo[i];
            p0 = (h > hthr0) || (h == hthr0 && lo >= lthr0);
            p1 = (h > hthr1) || (h == hthr1 && lo >= lthr1);
        }
        u32 b0 = __ballot_sync(0xFFFFFFFFu, p0);
        u32 b1 = __ballot_sync(0xFFFFFFFFu, p1);
        if (lane == 0) {
            s_hist0[tile * 32 + warp] = b0;
            s_hist1[tile * 32 + warp] = (u32)__popc(b0);
            if (b1) atomicMax(&s_fill, tile * bdim + warp * 32 + (31 - __clz(b1)));
        }
    }
    __syncthreads();
    {
        int nitems = ntiles * 32;  // <= 1024
        int v = (tid < nitems) ? (int)s_hist1[tid] : 0;
        int incl = block_scan_incl(v, lane, warp, s_w);
        if (tid < nitems) s_hist1[tid] = (u32)(incl - v);
        __syncthreads();
    }

    // ---- pass B: write outputs (no syncs) ----
    const u32 negk = mono32(NEG_FILL);
    float* idx_out = out;
    float* sc_out = out + (size_t)B * K * (1 + D);
    float* mk_out = sc_out + (size_t)B * K;
    int* gt = g_topidx + (size_t)b * N;
    const size_t obase = (size_t)b * K;

    for (int tile = 0; tile < ntiles; ++tile) {
        int i = tile * bdim + tid;
        if (i >= N) break;
        u32 bal = s_hist0[tile * 32 + warp];
        if ((bal >> lane) & 1u) {
            int j = (int)s_hist1[tile * 32 + warp]
                  + __popc(bal & ((1u << lane) - 1u));
            u32 h = s_hi[i];
            gt[j] = i;
            idx_out[obase + j] = (float)i;
            sc_out[obase + j] = inv_mono32(h);
            mk_out[obase + j] = (h != negk) ? 1.0f : 0.0f;
        }
    }

    // padding j in [num_keep, K): fill = max index among top-K
    int fill = s_fill;
    u32 kmf = s_hi[fill];
    float scf = inv_mono32(kmf);
    for (int j = num_keep + tid; j < K; j += bdim) {
        gt[j] = fill;
        idx_out[obase + j] = (float)fill;
        sc_out[obase + j] = scf;
        mk_out[obase + j] = 0.0f;
    }
}

// ---- Kernel 3: embedding gather ----
__global__ __launch_bounds__(256) void spanprune_gather(
    const float* __restrict__ emb, float* __restrict__ out_emb,
    int N, int D, int K, int total_vec)
{
    int t = blockIdx.x * blockDim.x + threadIdx.x;
    if (t >= total_vec) return;
    int per_row = D >> 2;
    int row = t / per_row;
    int c = t - row * per_row;
    int b = row / K;
    int j = row - b * K;
    int idx = g_topidx[b * N + j];
    float4 v = __ldg(&((const float4*)(emb + ((size_t)b * N + idx) * D))[c]);
    __stcs(&((float4*)(out_emb + (size_t)row * D))[c], v);
}

extern "C" void kernel_launch(void* const* d_in, const int* in_sizes, int n_in,
                              void* d_out, int out_size)
{
    const float* emb = (const float*)d_in[0];
    const float4* sa = (const float4*)d_in[1];
    const float4* sb = (const float4*)d_in[2];
    const void* sm = d_in[3];
    const int* sl = (const int*)d_in[4];

    int B = in_sizes[4];                 // 8
    int BN = in_sizes[3];                // B*N
    int N = BN / B;                      // 16384
    int D = in_sizes[0] / BN;            // 256
    int K = out_size / (B * (D + 3));    // max_keep

    prob_keys<<<(BN + 511) / 512, 256>>>(sa, sb, sm, BN, N - 1);

    size_t smem = (size_t)N * 10;  // hi + lo + 2 cand lists = 160 KB
    cudaFuncSetAttribute(spanprune_select,
                         cudaFuncAttributeMaxDynamicSharedMemorySize,
                         (int)smem);
    spanprune_select<<<B, 1024, smem>>>(sl, (float*)d_out, B, N, K, D);

    int total_vec = B * K * (D / 4);
    int threads = 256;
    int blocks = (total_vec + threads - 1) / threads;
    spanprune_gather<<<blocks, threads>>>(emb, (float*)d_out + (size_t)B * K,
                                          N, D, K, total_vec);
}

// round 8
// speedup vs baseline: 1.5150x; 1.1040x over previous
#include <cuda_runtime.h>
#include <stdint.h>

#define NEG_FILL -1e20f
#define MAXB 8
#define MAXN 16384
#define CH 16  // MAXN / 1024

typedef unsigned long long u64;
typedef unsigned int u32;
typedef unsigned short u16;

// scratch (no allocation allowed)
__device__ int g_topidx[MAXB * MAXN];
__device__ u32 g_hi[MAXB * MAXN];
__device__ u16 g_lo[MAXB * MAXN];
__device__ u32 g_hist[MAXB * 4096];

__device__ __forceinline__ u32 mono32(float f) {
    u32 u = __float_as_uint(f);
    return (u & 0x80000000u) ? ~u : (u | 0x80000000u);
}
__device__ __forceinline__ float inv_mono32(u32 k) {
    u32 u = (k & 0x80000000u) ? (k ^ 0x80000000u) : ~k;
    return __uint_as_float(u);
}

// prob = max over tags 1..7 of softmax over 8 tags == exp(m1-m)/Z
__device__ __forceinline__ float prob8(const float4* p) {
    float4 a = p[0], b = p[1];
    float m1 = fmaxf(fmaxf(a.y, a.z),
                     fmaxf(a.w, fmaxf(fmaxf(b.x, b.y), fmaxf(b.z, b.w))));
    float m = fmaxf(a.x, m1);
    float z = expf(a.x - m) + expf(a.y - m) + expf(a.z - m) + expf(a.w - m)
            + expf(b.x - m) + expf(b.y - m) + expf(b.z - m) + expf(b.w - m);
    return expf(m1 - m) / z;
}

// ---- Kernel 1: mask detect + prob + split keys + level-0 global hist ----
__global__ __launch_bounds__(256) void prob_keys(
    const float4* __restrict__ sa4, const float4* __restrict__ sb4,
    const void* __restrict__ mask, int BN, int N, int Nm1)
{
    __shared__ unsigned s_byte;
    const int i0 = blockIdx.x * 256;
    if (threadIdx.x == 0) s_byte = 0;
    __syncthreads();

    const u32* w = (const u32*)mask;
    if (threadIdx.x < 64) {
        u32 v = w[i0 / 4 + threadIdx.x];
        if (v != 0u && v != 1u && v != 0x3F800000u) atomicOr(&s_byte, 1u);
    }
    __syncthreads();
    const unsigned isbyte = s_byte;
    const unsigned char* mb = (const unsigned char*)mask;

    int i = i0 + threadIdx.x;
    int lane = threadIdx.x & 31;
    bool ok = i < BN;
    u32 h = 0, bin = 0;
    int b = 0;
    if (ok) {
        float p = fmaxf(prob8(sa4 + 2 * (size_t)i), prob8(sb4 + 2 * (size_t)i));
        bool m = isbyte ? (mb[i] != 0) : (w[i] != 0u);
        h = mono32(m ? p : NEG_FILL);
        g_hi[i] = h;
        g_lo[i] = (u16)(Nm1 - (i & Nm1));
        bin = h >> 20;
        b = i / N;
    }
    // warp-aggregated global hist atomic (block is within one batch)
    u32 msk = __ballot_sync(0xFFFFFFFFu, ok);
    if (ok) {
        u32 peers = __match_any_sync(msk, bin);
        if ((int)(__ffs(peers) - 1) == lane)
            atomicAdd(&g_hist[b * 4096 + bin], __popc(peers));
    }
}

// ---- block-wide inclusive scan ----
__device__ __forceinline__ int block_scan_incl(int v, int lane, int warp,
                                               int* s_w) {
    int acc = v;
    #pragma unroll
    for (int o = 1; o < 32; o <<= 1) {
        int x = __shfl_up_sync(0xFFFFFFFFu, acc, o);
        if (lane >= o) acc += x;
    }
    if (lane == 31) s_w[warp] = acc;
    __syncthreads();
    if (warp == 0) {
        int x = s_w[lane];
        #pragma unroll
        for (int o = 1; o < 32; o <<= 1) {
            int y = __shfl_up_sync(0xFFFFFFFFu, x, o);
            if (lane >= o) x += y;
        }
        s_w[lane] = x;
    }
    __syncthreads();
    int res = acc + (warp ? s_w[warp - 1] : 0);
    __syncthreads();
    return res;
}

// dual crossing search in ONE packed block scan (counts <= 16384 each)
__device__ __forceinline__ void find_digit2(const u32* hA, const u32* hB,
                                            int bins, int rA, int rB,
                                            int tid, int lane, int warp,
                                            int* s_w, int* s_bc) {
    int ipt = (bins + 1023) >> 10;  // <= 4
    u32 la[4], lb[4];
    u32 lsum = 0;
    int base = bins - 1 - tid * ipt;
    #pragma unroll
    for (int k = 0; k < 4; ++k) {
        int bb = base - k;
        bool v = (k < ipt && bb >= 0);
        la[k] = v ? hA[bb] : 0u;
        lb[k] = v ? hB[bb] : 0u;
        lsum += (la[k] << 16) | lb[k];
    }
    u32 incl = (u32)block_scan_incl((int)lsum, lane, warp, s_w);
    u32 cum = incl - lsum;
    int cumA = (int)(cum >> 16), cumB = (int)(cum & 0xFFFFu);
    #pragma unroll
    for (int k = 0; k < 4; ++k) {
        int bb = base - k;
        if (k < ipt && bb >= 0) {
            if (cumA < rA && cumA + (int)la[k] >= rA) { s_bc[0] = bb; s_bc[1] = cumA; }
            cumA += (int)la[k];
            if (cumB < rB && cumB + (int)lb[k] >= rB) { s_bc[2] = bb; s_bc[3] = cumB; }
            cumB += (int)lb[k];
        }
    }
    __syncthreads();
}

// dynamic smem: candidate 34-bit keys, N u64 (dual lists: front/back)
extern __shared__ u64 s_cand[];

__global__ __launch_bounds__(1024) void spanprune_select(
    const int* __restrict__ seq_length, float* __restrict__ out,
    int B, int N, int K, int D)
{
    __shared__ u32 s_hist0[4096];
    __shared__ u32 s_hist1[4096];
    __shared__ int s_w[32];
    __shared__ int s_bc[4];
    __shared__ int s_cnt[2];
    __shared__ int s_fill;
    __shared__ u32 s_kmf;

    const int b = blockIdx.x;
    const int tid = threadIdx.x;
    const int lane = tid & 31;
    const int warp = tid >> 5;

    int sl = seq_length[b];
    int num_keep = sl * 2;
    if (num_keep < 1) num_keep = 1;
    if (num_keep > K) num_keep = K;

    if (tid == 0) { s_fill = 0; s_cnt[0] = 0; s_cnt[1] = N; }

    // ---- level 0: both crossings straight from precomputed global hist ----
    const u32* gh_hist = g_hist + (size_t)b * 4096;
    int r0 = num_keep, r1 = K;
    find_digit2(gh_hist, gh_hist, 4096, r0, r1, tid, lane, warp, s_w, s_bc);
    u32 pfx0 = (u32)s_bc[0]; r0 -= s_bc[1];
    u32 pfx1 = (u32)s_bc[2]; r1 -= s_bc[3];
    bool sameb = (pfx0 == pfx1);
    __syncthreads();

    // ---- single full-N pass: hi -> registers, compact bin candidates ----
    const u32* ghi = g_hi + (size_t)b * N;
    const u16* glo = g_lo + (size_t)b * N;
    u32 hreg[CH];
    #pragma unroll
    for (int k = 0; k < CH; ++k) {
        int i = k * 1024 + tid;
        u32 h = __ldg(&ghi[i]);
        hreg[k] = h;
        u32 bin = h >> 20;
        if (bin == pfx0) {
            u32 lo = glo[i];
            int p = atomicAdd(&s_cnt[0], 1);
            s_cand[p] = (((u64)(h & 0xFFFFFu)) << 14) | lo;
        } else if (!sameb && bin == pfx1) {
            u32 lo = glo[i];
            int p = atomicAdd(&s_cnt[1], -1);
            s_cand[p - 1] = (((u64)(h & 0xFFFFFu)) << 14) | lo;
        }
    }
    __syncthreads();
    const int c0 = s_cnt[0];
    const int c1 = sameb ? c0 : (N - s_cnt[1]);
    const u64* cd0 = s_cand;
    const u64* cd1 = sameb ? s_cand : (s_cand + s_cnt[1]);
    __syncthreads();

    // ---- refine 34-bit candidate keys: 12 + 12 + 10 bits ----
    // level A: bits [33:22]
    for (int j = tid; j < 4096; j += 1024) { s_hist0[j] = 0; s_hist1[j] = 0; }
    __syncthreads();
    for (int i = tid; i < c0; i += 1024)
        atomicAdd(&s_hist0[(u32)(cd0[i] >> 22)], 1u);
    if (!sameb)
        for (int i = tid; i < c1; i += 1024)
            atomicAdd(&s_hist1[(u32)(cd1[i] >> 22)], 1u);
    __syncthreads();
    find_digit2(s_hist0, sameb ? s_hist0 : s_hist1, 4096, r0, r1,
                tid, lane, warp, s_w, s_bc);
    u32 a0 = (u32)s_bc[0]; r0 -= s_bc[1];
    u32 a1 = (u32)s_bc[2]; r1 -= s_bc[3];
    bool share = sameb && (a0 == a1);
    __syncthreads();

    // level B: bits [21:10], prefix = level-A digit
    for (int j = tid; j < 4096; j += 1024) { s_hist0[j] = 0; s_hist1[j] = 0; }
    __syncthreads();
    for (int i = tid; i < c0; i += 1024) {
        u64 v = cd0[i];
        if ((u32)(v >> 22) == a0) atomicAdd(&s_hist0[(u32)(v >> 10) & 4095u], 1u);
    }
    if (!share)
        for (int i = tid; i < c1; i += 1024) {
            u64 v = cd1[i];
            if ((u32)(v >> 22) == a1) atomicAdd(&s_hist1[(u32)(v >> 10) & 4095u], 1u);
        }
    __syncthreads();
    find_digit2(s_hist0, share ? s_hist0 : s_hist1, 4096, r0, r1,
                tid, lane, warp, s_w, s_bc);
    u32 b0d = (u32)s_bc[0]; r0 -= s_bc[1];
    u32 b1d = (u32)s_bc[2]; r1 -= s_bc[3];
    share = share && (b0d == b1d);
    u32 pA0 = (a0 << 12) | b0d;  // bits [33:10] of threshold 0
    u32 pA1 = (a1 << 12) | b1d;
    __syncthreads();

    // level C: bits [9:0]
    for (int j = tid; j < 1024; j += 1024) { s_hist0[j] = 0; s_hist1[j] = 0; }
    __syncthreads();
    for (int i = tid; i < c0; i += 1024) {
        u64 v = cd0[i];
        if ((u32)(v >> 10) == pA0) atomicAdd(&s_hist0[(u32)v & 1023u], 1u);
    }
    if (!share)
        for (int i = tid; i < c1; i += 1024) {
            u64 v = cd1[i];
            if ((u32)(v >> 10) == pA1) atomicAdd(&s_hist1[(u32)v & 1023u], 1u);
        }
    __syncthreads();
    find_digit2(s_hist0, share ? s_hist0 : s_hist1, 1024, r0, r1,
                tid, lane, warp, s_w, s_bc);
    u64 thr34_0 = ((u64)pA0 << 10) | (u32)s_bc[0];
    u64 thr34_1 = ((u64)pA1 << 10) | (u32)s_bc[2];

    const u32 hthr0 = (pfx0 << 20) | (u32)(thr34_0 >> 14);
    const u32 lthr0 = (u32)thr34_0 & 0x3FFFu;
    const u32 hthr1 = (pfx1 << 20) | (u32)(thr34_1 >> 14);
    const u32 lthr1 = (u32)thr34_1 & 0x3FFFu;
    __syncthreads();

    // ---- pass A: ballots + counts + fill (from registers) ----
    #pragma unroll
    for (int k = 0; k < CH; ++k) {
        int i = k * 1024 + tid;
        u32 h = hreg[k];
        bool p0, p1;
        if (h > hthr0) p0 = true;
        else if (h == hthr0) p0 = ((u32)glo[i] >= lthr0);
        else p0 = false;
        if (h > hthr1) p1 = true;
        else if (h == hthr1) p1 = ((u32)glo[i] >= lthr1);
        else p1 = false;
        u32 b0 = __ballot_sync(0xFFFFFFFFu, p0);
        u32 b1 = __ballot_sync(0xFFFFFFFFu, p1);
        if (lane == 0) {
            s_hist0[k * 32 + warp] = b0;
            s_hist1[k * 32 + warp] = (u32)__popc(b0);
            if (b1) atomicMax(&s_fill, k * 1024 + warp * 32 + (31 - __clz(b1)));
        }
    }
    __syncthreads();
    {   // exclusive scan of the 512 per-(tile,warp) counts
        int v = (tid < CH * 32) ? (int)s_hist1[tid] : 0;
        int incl = block_scan_incl(v, lane, warp, s_w);
        if (tid < CH * 32) s_hist1[tid] = (u32)(incl - v);
    }
    // owner of fill publishes its score bits
    int fill = s_fill;
    #pragma unroll
    for (int k = 0; k < CH; ++k)
        if (k * 1024 + tid == fill) s_kmf = hreg[k];
    __syncthreads();

    // ---- pass B: write outputs from registers (no syncs) ----
    const u32 negk = mono32(NEG_FILL);
    float* idx_out = out;
    float* sc_out = out + (size_t)B * K * (1 + D);
    float* mk_out = sc_out + (size_t)B * K;
    int* gt = g_topidx + (size_t)b * N;
    const size_t obase = (size_t)b * K;

    #pragma unroll
    for (int k = 0; k < CH; ++k) {
        int i = k * 1024 + tid;
        u32 bal = s_hist0[k * 32 + warp];
        if ((bal >> lane) & 1u) {
            int j = (int)s_hist1[k * 32 + warp]
                  + __popc(bal & ((1u << lane) - 1u));
            u32 h = hreg[k];
            gt[j] = i;
            idx_out[obase + j] = (float)i;
            sc_out[obase + j] = inv_mono32(h);
            mk_out[obase + j] = (h != negk) ? 1.0f : 0.0f;
        }
    }

    // padding j in [num_keep, K)
    u32 kmf = s_kmf;
    float scf = inv_mono32(kmf);
    for (int j = num_keep + tid; j < K; j += 1024) {
        gt[j] = fill;
        idx_out[obase + j] = (float)fill;
        sc_out[obase + j] = scf;
        mk_out[obase + j] = 0.0f;
    }
}

// ---- Kernel 3: embedding gather ----
__global__ __launch_bounds__(256) void spanprune_gather(
    const float* __restrict__ emb, float* __restrict__ out_emb,
    int N, int D, int K, int total_vec)
{
    int t = blockIdx.x * blockDim.x + threadIdx.x;
    if (t >= total_vec) return;
    int per_row = D >> 2;
    int row = t / per_row;
    int c = t - row * per_row;
    int b = row / K;
    int j = row - b * K;
    int idx = g_topidx[b * N + j];
    float4 v = __ldg(&((const float4*)(emb + ((size_t)b * N + idx) * D))[c]);
    __stcs(&((float4*)(out_emb + (size_t)row * D))[c], v);
}

extern "C" void kernel_launch(void* const* d_in, const int* in_sizes, int n_in,
                              void* d_out, int out_size)
{
    const float* emb = (const float*)d_in[0];
    const float4* sa = (const float4*)d_in[1];
    const float4* sb = (const float4*)d_in[2];
    const void* sm = d_in[3];
    const int* sl = (const int*)d_in[4];

    int B = in_sizes[4];                 // 8
    int BN = in_sizes[3];                // B*N
    int N = BN / B;                      // 16384
    int D = in_sizes[0] / BN;            // 256
    int K = out_size / (B * (D + 3));    // max_keep

    // zero the level-0 histograms (memset node; capture-legal, no alloc)
    void* hist_ptr = nullptr;
    cudaGetSymbolAddress(&hist_ptr, g_hist);
    cudaMemsetAsync(hist_ptr, 0, (size_t)B * 4096 * sizeof(u32));

    prob_keys<<<(BN + 255) / 256, 256>>>(sa, sb, sm, BN, N, N - 1);

    size_t smem = (size_t)N * sizeof(u64);  // 128 KB candidate buffer
    cudaFuncSetAttribute(spanprune_select,
                         cudaFuncAttributeMaxDynamicSharedMemorySize,
                         (int)smem);
    spanprune_select<<<B, 1024, smem>>>(sl, (float*)d_out, B, N, K, D);

    int total_vec = B * K * (D / 4);
    int threads = 256;
    int blocks = (total_vec + threads - 1) / threads;
    spanprune_gather<<<blocks, threads>>>(emb, (float*)d_out + (size_t)B * K,
                                          N, D, K, total_vec);
}

// round 9
// speedup vs baseline: 1.6388x; 1.0817x over previous
#include <cuda_runtime.h>
#include <stdint.h>

#define NEG_FILL -1e20f
#define MAXB 8
#define MAXN 16384
#define CH 16  // MAXN / 1024

typedef unsigned long long u64;
typedef unsigned int u32;
typedef unsigned short u16;

// scratch (no allocation allowed); zero-initialized at module load.
// g_hist invariant: zero at kernel_launch entry (select re-zeroes it).
__device__ int g_topidx[MAXB * MAXN];
__device__ u32 g_hi[MAXB * MAXN];
__device__ u32 g_hist[MAXB * 4096];

__device__ __forceinline__ u32 mono32(float f) {
    u32 u = __float_as_uint(f);
    return (u & 0x80000000u) ? ~u : (u | 0x80000000u);
}
__device__ __forceinline__ float inv_mono32(u32 k) {
    u32 u = (k & 0x80000000u) ? (k ^ 0x80000000u) : ~k;
    return __uint_as_float(u);
}

// prob = max over tags 1..7 of softmax over 8 tags.
// numerator exp(m1-m) == max(e1..e7) bitwise (exp monotone), saving one exp.
__device__ __forceinline__ float prob8(const float4* p) {
    float4 a = p[0], b = p[1];
    float m = fmaxf(fmaxf(fmaxf(a.x, a.y), fmaxf(a.z, a.w)),
                    fmaxf(fmaxf(b.x, b.y), fmaxf(b.z, b.w)));
    float e0 = expf(a.x - m);
    float e1 = expf(a.y - m), e2 = expf(a.z - m), e3 = expf(a.w - m);
    float e4 = expf(b.x - m), e5 = expf(b.y - m), e6 = expf(b.z - m);
    float e7 = expf(b.w - m);
    float num = fmaxf(fmaxf(fmaxf(e1, e2), fmaxf(e3, e4)),
                      fmaxf(fmaxf(e5, e6), e7));
    float z = ((e0 + e1) + (e2 + e3)) + ((e4 + e5) + (e6 + e7));
    return num / z;
}

// ---- Kernel 1: mask detect + prob + hi keys + level-0 global hist ----
__global__ __launch_bounds__(256) void prob_keys(
    const float4* __restrict__ sa4, const float4* __restrict__ sb4,
    const void* __restrict__ mask, int BN, int N)
{
    __shared__ unsigned s_byte;
    const int i0 = blockIdx.x * 256;
    if (threadIdx.x == 0) s_byte = 0;
    __syncthreads();

    const u32* w = (const u32*)mask;
    if (threadIdx.x < 64) {
        u32 v = w[i0 / 4 + threadIdx.x];
        if (v != 0u && v != 1u && v != 0x3F800000u) atomicOr(&s_byte, 1u);
    }
    __syncthreads();
    const unsigned isbyte = s_byte;
    const unsigned char* mb = (const unsigned char*)mask;

    int i = i0 + threadIdx.x;
    int lane = threadIdx.x & 31;
    bool ok = i < BN;
    u32 bin = 0;
    int b = 0;
    if (ok) {
        float p = fmaxf(prob8(sa4 + 2 * (size_t)i), prob8(sb4 + 2 * (size_t)i));
        bool m = isbyte ? (mb[i] != 0) : (w[i] != 0u);
        u32 h = mono32(m ? p : NEG_FILL);
        g_hi[i] = h;
        bin = h >> 20;
        b = i / N;
    }
    u32 msk = __ballot_sync(0xFFFFFFFFu, ok);
    if (ok) {
        u32 peers = __match_any_sync(msk, bin);
        if ((int)(__ffs(peers) - 1) == lane)
            atomicAdd(&g_hist[b * 4096 + bin], __popc(peers));
    }
}

// ---- block-wide inclusive scan ----
__device__ __forceinline__ int block_scan_incl(int v, int lane, int warp,
                                               int* s_w) {
    int acc = v;
    #pragma unroll
    for (int o = 1; o < 32; o <<= 1) {
        int x = __shfl_up_sync(0xFFFFFFFFu, acc, o);
        if (lane >= o) acc += x;
    }
    if (lane == 31) s_w[warp] = acc;
    __syncthreads();
    if (warp == 0) {
        int x = s_w[lane];
        #pragma unroll
        for (int o = 1; o < 32; o <<= 1) {
            int y = __shfl_up_sync(0xFFFFFFFFu, x, o);
            if (lane >= o) x += y;
        }
        s_w[lane] = x;
    }
    __syncthreads();
    int res = acc + (warp ? s_w[warp - 1] : 0);
    __syncthreads();
    return res;
}

// dual crossing search in ONE packed block scan (counts <= 16384 each)
__device__ __forceinline__ void find_digit2(const u32* hA, const u32* hB,
                                            int bins, int rA, int rB,
                                            int tid, int lane, int warp,
                                            int* s_w, int* s_bc) {
    int ipt = (bins + 1023) >> 10;  // <= 4
    u32 la[4], lb[4];
    u32 lsum = 0;
    int base = bins - 1 - tid * ipt;
    #pragma unroll
    for (int k = 0; k < 4; ++k) {
        int bb = base - k;
        bool v = (k < ipt && bb >= 0);
        la[k] = v ? hA[bb] : 0u;
        lb[k] = v ? hB[bb] : 0u;
        lsum += (la[k] << 16) | lb[k];
    }
    u32 incl = (u32)block_scan_incl((int)lsum, lane, warp, s_w);
    u32 cum = incl - lsum;
    int cumA = (int)(cum >> 16), cumB = (int)(cum & 0xFFFFu);
    #pragma unroll
    for (int k = 0; k < 4; ++k) {
        int bb = base - k;
        if (k < ipt && bb >= 0) {
            if (cumA < rA && cumA + (int)la[k] >= rA) { s_bc[0] = bb; s_bc[1] = cumA; }
            cumA += (int)la[k];
            if (cumB < rB && cumB + (int)lb[k] >= rB) { s_bc[2] = bb; s_bc[3] = cumB; }
            cumB += (int)lb[k];
        }
    }
    __syncthreads();
}

// dynamic smem: candidate 34-bit keys, N u64 (dual lists: front/back)
extern __shared__ u64 s_cand[];

__global__ __launch_bounds__(1024) void spanprune_select(
    const int* __restrict__ seq_length, float* __restrict__ out,
    int B, int N, int K, int D)
{
    __shared__ u32 s_hist0[4096];
    __shared__ u32 s_hist1[4096];
    __shared__ int s_w[32];
    __shared__ int s_bc[4];
    __shared__ int s_cnt[2];
    __shared__ int s_fill;
    __shared__ u32 s_kmf;

    const int b = blockIdx.x;
    const int tid = threadIdx.x;
    const int lane = tid & 31;
    const int warp = tid >> 5;
    const u32 Nm1 = (u32)(N - 1);

    int sl = seq_length[b];
    int num_keep = sl * 2;
    if (num_keep < 1) num_keep = 1;
    if (num_keep > K) num_keep = K;

    if (tid == 0) { s_fill = 0; s_cnt[0] = 0; s_cnt[1] = N; }

    // ---- level 0: both crossings from precomputed global hist ----
    u32* gh_hist = g_hist + (size_t)b * 4096;
    int r0 = num_keep, r1 = K;
    find_digit2(gh_hist, gh_hist, 4096, r0, r1, tid, lane, warp, s_w, s_bc);
    u32 pfx0 = (u32)s_bc[0]; r0 -= s_bc[1];
    u32 pfx1 = (u32)s_bc[2]; r1 -= s_bc[3];
    bool sameb = (pfx0 == pfx1);
    // restore the zero-at-entry invariant for the next launch (values consumed)
    for (int j = tid; j < 4096; j += 1024) gh_hist[j] = 0;
    __syncthreads();

    // ---- single full-N pass: hi -> registers, compact bin candidates ----
    const u32* ghi = g_hi + (size_t)b * N;
    u32 hreg[CH];
    #pragma unroll
    for (int k = 0; k < CH; ++k) {
        int i = k * 1024 + tid;
        u32 h = __ldg(&ghi[i]);
        hreg[k] = h;
        u32 bin = h >> 20;
        u32 lo = Nm1 - (u32)i;  // lo is a pure function of index
        if (bin == pfx0) {
            int p = atomicAdd(&s_cnt[0], 1);
            s_cand[p] = (((u64)(h & 0xFFFFFu)) << 14) | lo;
        } else if (!sameb && bin == pfx1) {
            int p = atomicAdd(&s_cnt[1], -1);
            s_cand[p - 1] = (((u64)(h & 0xFFFFFu)) << 14) | lo;
        }
    }
    __syncthreads();
    const int c0 = s_cnt[0];
    const int c1 = sameb ? c0 : (N - s_cnt[1]);
    const u64* cd0 = s_cand;
    const u64* cd1 = sameb ? s_cand : (s_cand + s_cnt[1]);
    __syncthreads();

    // ---- refine 34-bit candidate keys: 12 + 12 + 10 bits ----
    for (int j = tid; j < 4096; j += 1024) { s_hist0[j] = 0; s_hist1[j] = 0; }
    __syncthreads();
    for (int i = tid; i < c0; i += 1024)
        atomicAdd(&s_hist0[(u32)(cd0[i] >> 22)], 1u);
    if (!sameb)
        for (int i = tid; i < c1; i += 1024)
            atomicAdd(&s_hist1[(u32)(cd1[i] >> 22)], 1u);
    __syncthreads();
    find_digit2(s_hist0, sameb ? s_hist0 : s_hist1, 4096, r0, r1,
                tid, lane, warp, s_w, s_bc);
    u32 a0 = (u32)s_bc[0]; r0 -= s_bc[1];
    u32 a1 = (u32)s_bc[2]; r1 -= s_bc[3];
    bool share = sameb && (a0 == a1);
    __syncthreads();

    for (int j = tid; j < 4096; j += 1024) { s_hist0[j] = 0; s_hist1[j] = 0; }
    __syncthreads();
    for (int i = tid; i < c0; i += 1024) {
        u64 v = cd0[i];
        if ((u32)(v >> 22) == a0) atomicAdd(&s_hist0[(u32)(v >> 10) & 4095u], 1u);
    }
    if (!share)
        for (int i = tid; i < c1; i += 1024) {
            u64 v = cd1[i];
            if ((u32)(v >> 22) == a1) atomicAdd(&s_hist1[(u32)(v >> 10) & 4095u], 1u);
        }
    __syncthreads();
    find_digit2(s_hist0, share ? s_hist0 : s_hist1, 4096, r0, r1,
                tid, lane, warp, s_w, s_bc);
    u32 b0d = (u32)s_bc[0]; r0 -= s_bc[1];
    u32 b1d = (u32)s_bc[2]; r1 -= s_bc[3];
    share = share && (b0d == b1d);
    u32 pA0 = (a0 << 12) | b0d;
    u32 pA1 = (a1 << 12) | b1d;
    __syncthreads();

    if (tid < 1024) { s_hist0[tid] = 0; s_hist1[tid] = 0; }
    __syncthreads();
    for (int i = tid; i < c0; i += 1024) {
        u64 v = cd0[i];
        if ((u32)(v >> 10) == pA0) atomicAdd(&s_hist0[(u32)v & 1023u], 1u);
    }
    if (!share)
        for (int i = tid; i < c1; i += 1024) {
            u64 v = cd1[i];
            if ((u32)(v >> 10) == pA1) atomicAdd(&s_hist1[(u32)v & 1023u], 1u);
        }
    __syncthreads();
    find_digit2(s_hist0, share ? s_hist0 : s_hist1, 1024, r0, r1,
                tid, lane, warp, s_w, s_bc);
    u64 thr34_0 = ((u64)pA0 << 10) | (u32)s_bc[0];
    u64 thr34_1 = ((u64)pA1 << 10) | (u32)s_bc[2];

    const u32 hthr0 = (pfx0 << 20) | (u32)(thr34_0 >> 14);
    const u32 hthr1 = (pfx1 << 20) | (u32)(thr34_1 >> 14);
    // lo >= lthr  <=>  i <= imax  (lo = Nm1 - i)
    const int imax0 = (int)(Nm1 - ((u32)thr34_0 & 0x3FFFu));
    const int imax1 = (int)(Nm1 - ((u32)thr34_1 & 0x3FFFu));
    __syncthreads();

    // ---- pass A: ballots + counts + fill (from registers) ----
    #pragma unroll
    for (int k = 0; k < CH; ++k) {
        int i = k * 1024 + tid;
        u32 h = hreg[k];
        bool p0 = (h > hthr0) || (h == hthr0 && i <= imax0);
        bool p1 = (h > hthr1) || (h == hthr1 && i <= imax1);
        u32 b0 = __ballot_sync(0xFFFFFFFFu, p0);
        u32 b1 = __ballot_sync(0xFFFFFFFFu, p1);
        if (lane == 0) {
            s_hist0[k * 32 + warp] = b0;
            s_hist1[k * 32 + warp] = (u32)__popc(b0);
            if (b1) atomicMax(&s_fill, k * 1024 + warp * 32 + (31 - __clz(b1)));
        }
    }
    __syncthreads();
    {   // exclusive scan of the 512 per-(tile,warp) counts
        int v = (tid < CH * 32) ? (int)s_hist1[tid] : 0;
        int incl = block_scan_incl(v, lane, warp, s_w);
        if (tid < CH * 32) s_hist1[tid] = (u32)(incl - v);
    }
    int fill = s_fill;
    #pragma unroll
    for (int k = 0; k < CH; ++k)
        if (k * 1024 + tid == fill) s_kmf = hreg[k];
    __syncthreads();

    // ---- pass B: write outputs from registers (no syncs) ----
    const u32 negk = mono32(NEG_FILL);
    float* idx_out = out;
    float* sc_out = out + (size_t)B * K * (1 + D);
    float* mk_out = sc_out + (size_t)B * K;
    int* gt = g_topidx + (size_t)b * N;
    const size_t obase = (size_t)b * K;

    #pragma unroll
    for (int k = 0; k < CH; ++k) {
        int i = k * 1024 + tid;
        u32 bal = s_hist0[k * 32 + warp];
        if ((bal >> lane) & 1u) {
            int j = (int)s_hist1[k * 32 + warp]
                  + __popc(bal & ((1u << lane) - 1u));
            u32 h = hreg[k];
            gt[j] = i;
            idx_out[obase + j] = (float)i;
            sc_out[obase + j] = inv_mono32(h);
            mk_out[obase + j] = (h != negk) ? 1.0f : 0.0f;
        }
    }

    u32 kmf = s_kmf;
    float scf = inv_mono32(kmf);
    for (int j = num_keep + tid; j < K; j += 1024) {
        gt[j] = fill;
        idx_out[obase + j] = (float)fill;
        sc_out[obase + j] = scf;
        mk_out[obase + j] = 0.0f;
    }
}

// ---- Kernel 3: embedding gather (2 float4 per thread) ----
__global__ __launch_bounds__(256) void spanprune_gather(
    const float* __restrict__ emb, float* __restrict__ out_emb,
    int N, int D, int K, int total_pairs)
{
    int t = blockIdx.x * blockDim.x + threadIdx.x;
    if (t >= total_pairs) return;
    int ppr = D >> 3;  // float4-pairs per row
    int row = t / ppr;
    int c = (t - row * ppr) * 2;
    int b = row / K;
    int j = row - b * K;
    int idx = g_topidx[b * N + j];
    const float4* src = (const float4*)(emb + ((size_t)b * N + idx) * D);
    float4* dst = (float4*)(out_emb + (size_t)row * D);
    float4 v0 = __ldg(&src[c]);
    float4 v1 = __ldg(&src[c + 1]);
    __stcs(&dst[c], v0);
    __stcs(&dst[c + 1], v1);
}

extern "C" void kernel_launch(void* const* d_in, const int* in_sizes, int n_in,
                              void* d_out, int out_size)
{
    const float* emb = (const float*)d_in[0];
    const float4* sa = (const float4*)d_in[1];
    const float4* sb = (const float4*)d_in[2];
    const void* sm = d_in[3];
    const int* sl = (const int*)d_in[4];

    int B = in_sizes[4];                 // 8
    int BN = in_sizes[3];                // B*N
    int N = BN / B;                      // 16384
    int D = in_sizes[0] / BN;            // 256
    int K = out_size / (B * (D + 3));    // max_keep

    prob_keys<<<(BN + 255) / 256, 256>>>(sa, sb, sm, BN, N);

    size_t smem = (size_t)N * sizeof(u64);  // 128 KB candidate buffer
    cudaFuncSetAttribute(spanprune_select,
                         cudaFuncAttributeMaxDynamicSharedMemorySize,
                         (int)smem);
    spanprune_select<<<B, 1024, smem>>>(sl, (float*)d_out, B, N, K, D);

    int total_pairs = B * K * (D / 8);
    int threads = 256;
    int blocks = (total_pairs + threads - 1) / threads;
    spanprune_gather<<<blocks, threads>>>(emb, (float*)d_out + (size_t)B * K,
                                          N, D, K, total_pairs);
}